// round 5
// baseline (speedup 1.0000x reference)
#include <cuda_runtime.h>
#include <math.h>

#define DD 2048
#define SS 8192
#define SD (SS*DD)
#define INNER_LR 0.01f

// ---------------- device scratch (static globals; no allocation) ----------------
__device__ float g_q[SD];
__device__ float g_k[SD];
__device__ float g_v[SD];
__device__ float g_h[SD];
__device__ float g_a[SD];
__device__ float g_dy[SD];   // y, then dy in place
__device__ float g_dh[SD];   // da, then dh in place
__device__ float g_T1[SD];   // transpose scratch
__device__ float g_T2[SD];   // transpose scratch
__device__ float g_W2T[DD*DD];
__device__ float g_gW1[DD*DD];
__device__ float g_gW2[DD*DD];
__device__ float g_W1f[DD*DD];
__device__ float g_W2f[DD*DD];
__device__ float g_b1f[DD];
__device__ float g_b2f[DD];
__device__ float g_gb1[DD];
__device__ float g_gb2[DD];
__device__ float g_part[2048];
__device__ float g_alpha;

// ---------------- GEMM: C[M,N] = A[M,K] @ B[N,K]^T (+ bias[n]) ----------------
// All row-major with leading dim = K (A,B) / N (C). M,N multiples of 128; K multiple of 16.
__global__ void __launch_bounds__(256) gemm_nt(
    const float* __restrict__ A, const float* __restrict__ B,
    float* __restrict__ C, const float* __restrict__ bias,
    int Mh, int Nh, int Kh)
{
    __shared__ float As[16][132];
    __shared__ float Bs[16][132];
    const int tid = threadIdx.x;
    const int tx = tid & 15, ty = tid >> 4;
    const int m0 = blockIdx.y * 128, n0 = blockIdx.x * 128;

    float acc[8][8];
#pragma unroll
    for (int i = 0; i < 8; i++)
#pragma unroll
        for (int j = 0; j < 8; j++) acc[i][j] = 0.f;

    for (int k0 = 0; k0 < Kh; k0 += 16) {
#pragma unroll
        for (int v = 0; v < 2; v++) {
            int idx = tid + v * 256;      // 0..511
            int m   = idx >> 2;           // 0..127
            int kq  = (idx & 3) << 2;     // 0,4,8,12
            float4 av = *(const float4*)(A + (size_t)(m0 + m) * Kh + k0 + kq);
            As[kq + 0][m] = av.x; As[kq + 1][m] = av.y;
            As[kq + 2][m] = av.z; As[kq + 3][m] = av.w;
            float4 bv = *(const float4*)(B + (size_t)(n0 + m) * Kh + k0 + kq);
            Bs[kq + 0][m] = bv.x; Bs[kq + 1][m] = bv.y;
            Bs[kq + 2][m] = bv.z; Bs[kq + 3][m] = bv.w;
        }
        __syncthreads();
#pragma unroll
        for (int kk = 0; kk < 16; kk++) {
            float ar[8], br[8];
#pragma unroll
            for (int i = 0; i < 8; i++) ar[i] = As[kk][ty * 8 + i];
#pragma unroll
            for (int j = 0; j < 8; j++) br[j] = Bs[kk][tx * 8 + j];
#pragma unroll
            for (int i = 0; i < 8; i++)
#pragma unroll
                for (int j = 0; j < 8; j++)
                    acc[i][j] = fmaf(ar[i], br[j], acc[i][j]);
        }
        __syncthreads();
    }

#pragma unroll
    for (int i = 0; i < 8; i++) {
        int row = m0 + ty * 8 + i;
#pragma unroll
        for (int j = 0; j < 8; j++) {
            int col = n0 + tx * 8 + j;
            float r = acc[i][j];
            if (bias) r += bias[col];
            C[(size_t)row * Nh + col] = r;
        }
    }
}

// ---------------- transpose: out[C,R] = in[R,C]^T (R,C multiples of 32) ----------------
__global__ void __launch_bounds__(256) transpose_k(
    const float* __restrict__ in, float* __restrict__ out, int R, int Ccols)
{
    __shared__ float tile[32][33];
    int cb = blockIdx.x * 32, rb = blockIdx.y * 32;
    int tx = threadIdx.x & 31, ty = threadIdx.x >> 5;  // 32x8
#pragma unroll
    for (int i = 0; i < 32; i += 8)
        tile[ty + i][tx] = in[(size_t)(rb + ty + i) * Ccols + cb + tx];
    __syncthreads();
#pragma unroll
    for (int i = 0; i < 32; i += 8)
        out[(size_t)(cb + ty + i) * R + rb + tx] = tile[tx][ty + i];
}

// ---------------- row l2-normalize in place: X[r,:] /= max(||X[r,:]||, 1e-12) ----------------
__global__ void __launch_bounds__(256) rownorm_k(float* __restrict__ X)
{
    __shared__ float red[256];
    int r = blockIdx.x;
    int t = threadIdx.x;
    float ss = 0.f;
    for (int c = t; c < DD; c += 256) {
        float v = X[(size_t)r * DD + c];
        ss += v * v;
    }
    red[t] = ss;
    __syncthreads();
    for (int s = 128; s > 0; s >>= 1) {
        if (t < s) red[t] += red[t + s];
        __syncthreads();
    }
    float sc = 1.0f / fmaxf(sqrtf(red[0]), 1e-12f);
    for (int c = t; c < DD; c += 256)
        X[(size_t)r * DD + c] *= sc;
}

// ---------------- elementwise ----------------
__global__ void __launch_bounds__(256) silu_k(const float* __restrict__ h, float* __restrict__ a)
{
    size_t i = (size_t)blockIdx.x * 256 + threadIdx.x;
    float x = h[i];
    float sg = 1.0f / (1.0f + expf(-x));
    a[i] = x * sg;
}

__global__ void __launch_bounds__(256) make_dy_k(const float* __restrict__ v, float* __restrict__ y)
{
    size_t i = (size_t)blockIdx.x * 256 + threadIdx.x;
    y[i] = (y[i] - v[i]) * (2.0f / (float)SD);
}

__global__ void __launch_bounds__(256) make_dh_k(const float* __restrict__ h, float* __restrict__ dh)
{
    size_t i = (size_t)blockIdx.x * 256 + threadIdx.x;
    float x = h[i];
    float sg = 1.0f / (1.0f + expf(-x));
    float ds = sg * (1.0f + x * (1.0f - sg));
    dh[i] *= ds;
}

// ---------------- column sum: out[c] = sum_r M[r,c] ----------------
__global__ void __launch_bounds__(256) colsum_k(const float* __restrict__ M, float* __restrict__ out)
{
    int c = blockIdx.x * 256 + threadIdx.x;
    float s0 = 0.f, s1 = 0.f, s2 = 0.f, s3 = 0.f;
    for (int r = 0; r < SS; r += 4) {
        s0 += M[(size_t)(r + 0) * DD + c];
        s1 += M[(size_t)(r + 1) * DD + c];
        s2 += M[(size_t)(r + 2) * DD + c];
        s3 += M[(size_t)(r + 3) * DD + c];
    }
    out[c] = (s0 + s1) + (s2 + s3);
}

// ---------------- alpha = sigmoid((1/S) * sum_{s,d} x[s,d]*aw[d] + ab) ----------------
__global__ void __launch_bounds__(256) alpha_partial_k(
    const float* __restrict__ x, const float* __restrict__ aw)
{
    __shared__ float red[256];
    int b = blockIdx.x;               // 2048 blocks, each covers 8192 contiguous elems (4 rows)
    size_t base = (size_t)b * 8192;
    int t = threadIdx.x;
    float s = 0.f;
    for (int i = t; i < 8192; i += 256)
        s += x[base + i] * aw[i & (DD - 1)];
    red[t] = s;
    __syncthreads();
    for (int k = 128; k > 0; k >>= 1) {
        if (t < k) red[t] += red[t + k];
        __syncthreads();
    }
    if (t == 0) g_part[b] = red[0];
}

__global__ void __launch_bounds__(256) alpha_final_k(const float* __restrict__ ab)
{
    __shared__ float red[256];
    int t = threadIdx.x;
    float s = 0.f;
    for (int i = t; i < 2048; i += 256) s += g_part[i];
    red[t] = s;
    __syncthreads();
    for (int k = 128; k > 0; k >>= 1) {
        if (t < k) red[t] += red[t + k];
        __syncthreads();
    }
    if (t == 0) {
        float pre = red[0] / (float)SS + ab[0];
        g_alpha = 1.0f / (1.0f + expf(-pre));
    }
}

// ---------------- fast weights ----------------
__global__ void __launch_bounds__(256) fastw_k(
    const float* __restrict__ W, const float* __restrict__ Gm, float* __restrict__ Wf)
{
    size_t i = (size_t)blockIdx.x * 256 + threadIdx.x;
    float am1 = 1.0f - g_alpha;
    Wf[i] = am1 * W[i] - INNER_LR * Gm[i];
}

__global__ void __launch_bounds__(256) fastb_k(
    const float* __restrict__ b1, const float* __restrict__ gb1, float* __restrict__ b1f,
    const float* __restrict__ b2, const float* __restrict__ gb2, float* __restrict__ b2f)
{
    int i = blockIdx.x * 256 + threadIdx.x;
    float am1 = 1.0f - g_alpha;
    b1f[i] = am1 * b1[i] - INNER_LR * gb1[i];
    b2f[i] = am1 * b2[i] - INNER_LR * gb2[i];
}

// ---------------- launch ----------------
extern "C" void kernel_launch(void* const* d_in, const int* in_sizes, int n_in,
                              void* d_out, int out_size)
{
    const float* x   = (const float*)d_in[0];
    const float* W_Q = (const float*)d_in[1];
    const float* W_K = (const float*)d_in[2];
    const float* W_V = (const float*)d_in[3];
    const float* aw  = (const float*)d_in[4];
    const float* ab  = (const float*)d_in[5];
    const float* W1  = (const float*)d_in[6];
    const float* b1  = (const float*)d_in[7];
    const float* W2  = (const float*)d_in[8];
    const float* b2  = (const float*)d_in[9];
    float* out = (float*)d_out;

    float *p_q, *p_k, *p_v, *p_h, *p_a, *p_dy, *p_dh, *p_T1, *p_T2;
    float *p_W2T, *p_gW1, *p_gW2, *p_W1f, *p_W2f, *p_b1f, *p_b2f, *p_gb1, *p_gb2;
    cudaGetSymbolAddress((void**)&p_q,  g_q);
    cudaGetSymbolAddress((void**)&p_k,  g_k);
    cudaGetSymbolAddress((void**)&p_v,  g_v);
    cudaGetSymbolAddress((void**)&p_h,  g_h);
    cudaGetSymbolAddress((void**)&p_a,  g_a);
    cudaGetSymbolAddress((void**)&p_dy, g_dy);
    cudaGetSymbolAddress((void**)&p_dh, g_dh);
    cudaGetSymbolAddress((void**)&p_T1, g_T1);
    cudaGetSymbolAddress((void**)&p_T2, g_T2);
    cudaGetSymbolAddress((void**)&p_W2T, g_W2T);
    cudaGetSymbolAddress((void**)&p_gW1, g_gW1);
    cudaGetSymbolAddress((void**)&p_gW2, g_gW2);
    cudaGetSymbolAddress((void**)&p_W1f, g_W1f);
    cudaGetSymbolAddress((void**)&p_W2f, g_W2f);
    cudaGetSymbolAddress((void**)&p_b1f, g_b1f);
    cudaGetSymbolAddress((void**)&p_b2f, g_b2f);
    cudaGetSymbolAddress((void**)&p_gb1, g_gb1);
    cudaGetSymbolAddress((void**)&p_gb2, g_gb2);

    dim3 blk(256);
    dim3 gSD(DD / 128, SS / 128);   // M=S, N=D GEMMs
    dim3 gDD(DD / 128, DD / 128);   // M=D, N=D GEMMs (K=S)
    int ewBlocks = SD / 256;
    dim3 tSD(DD / 32, SS / 32);     // transpose [S,D] -> [D,S]
    dim3 tDD(DD / 32, DD / 32);

    // alpha = sigmoid(mean(x,1) @ aw^T + ab)
    alpha_partial_k<<<2048, blk>>>(x, aw);
    alpha_final_k<<<1, blk>>>(ab);

    // q,k,v projections
    gemm_nt<<<gSD, blk>>>(x, W_Q, p_q, nullptr, SS, DD, DD);
    gemm_nt<<<gSD, blk>>>(x, W_K, p_k, nullptr, SS, DD, DD);
    gemm_nt<<<gSD, blk>>>(x, W_V, p_v, nullptr, SS, DD, DD);
    rownorm_k<<<SS, blk>>>(p_q);
    rownorm_k<<<SS, blk>>>(p_k);

    // forward mlp on k
    gemm_nt<<<gSD, blk>>>(p_k, W1, p_h, b1, SS, DD, DD);
    silu_k<<<ewBlocks, blk>>>(p_h, p_a);
    gemm_nt<<<gSD, blk>>>(p_a, W2, p_dy, b2, SS, DD, DD);   // y
    make_dy_k<<<ewBlocks, blk>>>(p_v, p_dy);                 // dy = 2(y-v)/(S*D)

    // gW2 = dy^T @ a ; gb2
    transpose_k<<<tSD, blk>>>(p_dy, p_T1, SS, DD);
    transpose_k<<<tSD, blk>>>(p_a,  p_T2, SS, DD);
    gemm_nt<<<gDD, blk>>>(p_T1, p_T2, p_gW2, nullptr, DD, DD, SS);
    colsum_k<<<DD / 256, blk>>>(p_dy, p_gb2);

    // da = dy @ W2 ; dh = da * dsilu(h)
    transpose_k<<<tDD, blk>>>(W2, p_W2T, DD, DD);
    gemm_nt<<<gSD, blk>>>(p_dy, p_W2T, p_dh, nullptr, SS, DD, DD);
    make_dh_k<<<ewBlocks, blk>>>(p_h, p_dh);

    // gW1 = dh^T @ k ; gb1
    transpose_k<<<tSD, blk>>>(p_dh, p_T1, SS, DD);
    transpose_k<<<tSD, blk>>>(p_k,  p_T2, SS, DD);
    gemm_nt<<<gDD, blk>>>(p_T1, p_T2, p_gW1, nullptr, DD, DD, SS);
    colsum_k<<<DD / 256, blk>>>(p_dh, p_gb1);

    // fast weights
    fastw_k<<<(DD * DD) / 256, blk>>>(W1, p_gW1, p_W1f);
    fastw_k<<<(DD * DD) / 256, blk>>>(W2, p_gW2, p_W2f);
    fastb_k<<<DD / 256, blk>>>(b1, p_gb1, p_b1f, b2, p_gb2, p_b2f);

    // retrieve: out = silu(q @ W1f^T + b1f) @ W2f^T + b2f
    gemm_nt<<<gSD, blk>>>(p_q, p_W1f, p_h, p_b1f, SS, DD, DD);
    silu_k<<<ewBlocks, blk>>>(p_h, p_a);
    gemm_nt<<<gSD, blk>>>(p_a, p_W2f, out, p_b2f, SS, DD, DD);
}

// round 9
// speedup vs baseline: 4.0782x; 4.0782x over previous
#include <cuda_runtime.h>
#include <cuda_bf16.h>
#include <math.h>
#include <stdint.h>

#define DD 2048
#define SS 8192
#define SD (SS*DD)
#define DD2 (DD*DD)
#define INNER_LR 0.01f

// ---------------- scratch arenas ----------------
#define F_Q   ((size_t)0*SD)
#define F_K   ((size_t)1*SD)
#define F_V   ((size_t)2*SD)
#define F_H   ((size_t)3*SD)
#define F_A   ((size_t)4*SD)
#define F_DY  ((size_t)5*SD)
#define F_DH  ((size_t)6*SD)
#define F_GW1 ((size_t)7*SD)
#define F_GW2 (F_GW1 + DD2)
#define F_W1F (F_GW2 + DD2)
#define F_W2F (F_W1F + DD2)
#define F_B1F (F_W2F + DD2)
#define F_B2F (F_B1F + DD)
#define F_GB1 (F_B2F + DD)
#define F_GB2 (F_GB1 + DD)
#define F_PART (F_GB2 + DD)
#define F_ALPHA (F_PART + 2048)
#define F_TOTAL (F_ALPHA + 64)
__device__ float g_f32[F_TOTAL];

#define B_XH   ((size_t)0*SD)
#define B_XL   ((size_t)1*SD)
#define B_QH   ((size_t)2*SD)
#define B_QL   ((size_t)3*SD)
#define B_K    ((size_t)4*SD)
#define B_KT   ((size_t)5*SD)
#define B_A    ((size_t)6*SD)
#define B_AT   ((size_t)7*SD)
#define B_DY   ((size_t)8*SD)
#define B_DYT  ((size_t)9*SD)
#define B_DHT  ((size_t)10*SD)
#define B_ARH  ((size_t)11*SD)
#define B_ARL  ((size_t)12*SD)
#define B_W    ((size_t)13*SD)
#define B_WQH  (B_W + (size_t)0*DD2)
#define B_WQL  (B_W + (size_t)1*DD2)
#define B_WK   (B_W + (size_t)2*DD2)
#define B_WV   (B_W + (size_t)3*DD2)
#define B_W1   (B_W + (size_t)4*DD2)
#define B_W2   (B_W + (size_t)5*DD2)
#define B_W2T  (B_W + (size_t)6*DD2)
#define B_W1FH (B_W + (size_t)7*DD2)
#define B_W1FL (B_W + (size_t)8*DD2)
#define B_W2FH (B_W + (size_t)9*DD2)
#define B_W2FL (B_W + (size_t)10*DD2)
#define B_TOTAL (B_W + (size_t)11*DD2)
__device__ __nv_bfloat16 g_bf[B_TOTAL];

// ---------------- PTX helpers (compute_80+ baseline only) ----------------
__device__ __forceinline__ uint32_t smem_u32(const void* p) {
    uint32_t a;
    asm("{ .reg .u64 t; cvta.to.shared.u64 t, %1; cvt.u32.u64 %0, t; }" : "=r"(a) : "l"(p));
    return a;
}
__device__ __forceinline__ void cp16(uint32_t s, const void* g) {
    asm volatile("cp.async.cg.shared.global [%0], [%1], 16;" :: "r"(s), "l"(g) : "memory");
}
__device__ __forceinline__ void cp_commit() {
    asm volatile("cp.async.commit_group;" ::: "memory");
}
__device__ __forceinline__ void ldm4(uint32_t* r, uint32_t a) {
    asm volatile("ldmatrix.sync.aligned.m8n8.x4.shared.b16 {%0,%1,%2,%3}, [%4];"
                 : "=r"(r[0]), "=r"(r[1]), "=r"(r[2]), "=r"(r[3]) : "r"(a));
}
__device__ __forceinline__ void mma16816(float* d, const uint32_t* a, uint32_t b0, uint32_t b1) {
    asm volatile("mma.sync.aligned.m16n8k16.row.col.f32.bf16.bf16.f32 "
        "{%0,%1,%2,%3}, {%4,%5,%6,%7}, {%8,%9}, {%0,%1,%2,%3};"
        : "+f"(d[0]), "+f"(d[1]), "+f"(d[2]), "+f"(d[3])
        : "r"(a[0]), "r"(a[1]), "r"(a[2]), "r"(a[3]), "r"(b0), "r"(b1));
}
// swizzled smem offset (bytes) for [row][chunk16B c], 64B rows, 4 chunks
__device__ __forceinline__ uint32_t swz(int row, int c) {
    return (uint32_t)(row * 64 + ((c ^ (row & 3)) << 4));
}

// ---------------- mma.sync GEMM: C[M,N] = A[M,K] @ B[N,K]^T (+bias | +=) ----------------
// Block 128x128, BK=32, 8 warps (4x2), warp tile 32x64. A,B bf16 K-major.
template <int ACCUM>
__global__ void __launch_bounds__(256) gemm_mma(
    const __nv_bfloat16* __restrict__ A, const __nv_bfloat16* __restrict__ B,
    float* __restrict__ C, const float* __restrict__ bias, int Nw, int K)
{
    __shared__ __align__(128) __nv_bfloat16 smbuf[2][2][128 * 32];
    const int tid = threadIdx.x;
    const int lane = tid & 31, wid = tid >> 5;
    const int wr = wid >> 1, wc = wid & 1;
    const int m0 = blockIdx.y * 128, n0 = blockIdx.x * 128;

    const uint32_t smA = smem_u32(&smbuf[0][0][0]);
    const uint32_t STG = 16384u, OFB = 8192u;

    // cp.async assignments: 2 A chunks + 2 B chunks per thread
    uint32_t so[2]; size_t goA[2], goB[2];
#pragma unroll
    for (int i = 0; i < 2; i++) {
        int ch = tid * 2 + i, row = ch >> 2, c = ch & 3;
        so[i] = swz(row, c);
        goA[i] = (size_t)(m0 + row) * K + c * 8;
        goB[i] = (size_t)(n0 + row) * K + c * 8;
    }
    auto issue = [&](int ck, int s) {
        int k0 = ck << 5;
        uint32_t sb = smA + (uint32_t)s * STG;
#pragma unroll
        for (int i = 0; i < 2; i++) cp16(sb + so[i], A + goA[i] + k0);
#pragma unroll
        for (int i = 0; i < 2; i++) cp16(sb + OFB + so[i], B + goB[i] + k0);
        cp_commit();
    };

    // ldmatrix lane addressing (within-tile row & chunk), A: m16k16, B: n16k16
    const int laA = lane & 15, lcA = lane >> 4;                 // row, k-half
    const int laB = (lane & 7) + ((lane >> 4) << 3);            // n row
    const int lcB = (lane >> 3) & 1;                            // k-half

    float acc[2][8][4];
#pragma unroll
    for (int mt = 0; mt < 2; mt++)
#pragma unroll
        for (int nt = 0; nt < 8; nt++)
#pragma unroll
            for (int j = 0; j < 4; j++) acc[mt][nt][j] = 0.f;

    const int nk = K >> 5;
    issue(0, 0);

    for (int ck = 0; ck < nk; ck++) {
        int s = ck & 1;
        bool more = (ck + 1 < nk);
        if (more) issue(ck + 1, s ^ 1);
        if (more) asm volatile("cp.async.wait_group 1;" ::: "memory");
        else      asm volatile("cp.async.wait_group 0;" ::: "memory");
        __syncthreads();

        uint32_t sbA = smA + (uint32_t)s * STG;
        uint32_t sbB = sbA + OFB;
#pragma unroll
        for (int ks = 0; ks < 2; ks++) {
            uint32_t af[2][4], bf[4][4];
#pragma unroll
            for (int mt = 0; mt < 2; mt++)
                ldm4(af[mt], sbA + swz(wr * 32 + mt * 16 + laA, ks * 2 + lcA));
#pragma unroll
            for (int bt = 0; bt < 4; bt++)
                ldm4(bf[bt], sbB + swz(wc * 64 + bt * 16 + laB, ks * 2 + lcB));
#pragma unroll
            for (int mt = 0; mt < 2; mt++)
#pragma unroll
                for (int nt = 0; nt < 8; nt++) {
                    const uint32_t* bp = bf[nt >> 1];
                    if (nt & 1) mma16816(acc[mt][nt], af[mt], bp[2], bp[3]);
                    else        mma16816(acc[mt][nt], af[mt], bp[0], bp[1]);
                }
        }
        __syncthreads();   // all reads of stage s done before it is refilled
    }

    // epilogue
#pragma unroll
    for (int mt = 0; mt < 2; mt++) {
        int r = m0 + wr * 32 + mt * 16 + (lane >> 2);
#pragma unroll
        for (int nt = 0; nt < 8; nt++) {
            int col = n0 + wc * 64 + nt * 8 + (lane & 3) * 2;
            float bx = 0.f, by = 0.f;
            if (bias) { bx = bias[col]; by = bias[col + 1]; }
            float2* p0 = (float2*)(C + (size_t)r * Nw + col);
            float2* p1 = (float2*)(C + (size_t)(r + 8) * Nw + col);
            float2 v0, v1;
            if (ACCUM) {
                float2 o0 = *p0, o1 = *p1;
                v0 = make_float2(o0.x + acc[mt][nt][0], o0.y + acc[mt][nt][1]);
                v1 = make_float2(o1.x + acc[mt][nt][2], o1.y + acc[mt][nt][3]);
            } else {
                v0 = make_float2(acc[mt][nt][0] + bx, acc[mt][nt][1] + by);
                v1 = make_float2(acc[mt][nt][2] + bx, acc[mt][nt][3] + by);
            }
            *p0 = v0; *p1 = v1;
        }
    }
}

// ---------------- conversions ----------------
__global__ void __launch_bounds__(256) cvt_k(const float4* __restrict__ in,
                                             __nv_bfloat162* __restrict__ out)
{
    size_t i = (size_t)blockIdx.x * 256 + threadIdx.x;
    float4 v = in[i];
    out[2*i]   = __floats2bfloat162_rn(v.x, v.y);
    out[2*i+1] = __floats2bfloat162_rn(v.z, v.w);
}
__global__ void __launch_bounds__(256) cvt_split_k(const float4* __restrict__ in,
                                                   __nv_bfloat162* __restrict__ oh,
                                                   __nv_bfloat162* __restrict__ ol)
{
    size_t i = (size_t)blockIdx.x * 256 + threadIdx.x;
    float4 v = in[i];
    float f[4] = { v.x, v.y, v.z, v.w };
    __nv_bfloat16 h[4], l[4];
#pragma unroll
    for (int j = 0; j < 4; j++) {
        h[j] = __float2bfloat16(f[j]);
        l[j] = __float2bfloat16(f[j] - __bfloat162float(h[j]));
    }
    oh[2*i]   = __nv_bfloat162(h[0], h[1]);
    oh[2*i+1] = __nv_bfloat162(h[2], h[3]);
    ol[2*i]   = __nv_bfloat162(l[0], l[1]);
    ol[2*i+1] = __nv_bfloat162(l[2], l[3]);
}
__global__ void __launch_bounds__(256) cvtT_k(const float* __restrict__ in,
                                              __nv_bfloat16* __restrict__ out, int R, int Cc)
{
    __shared__ float tile[32][33];
    int cb = blockIdx.x * 32, rb = blockIdx.y * 32;
    int tx = threadIdx.x & 31, ty = threadIdx.x >> 5;
#pragma unroll
    for (int i = 0; i < 32; i += 8)
        tile[ty + i][tx] = in[(size_t)(rb + ty + i) * Cc + cb + tx];
    __syncthreads();
#pragma unroll
    for (int i = 0; i < 32; i += 8)
        out[(size_t)(cb + ty + i) * R + rb + tx] = __float2bfloat16(tile[tx][ty + i]);
}

// ---------------- small fp32 kernels ----------------
__global__ void __launch_bounds__(256) rownorm_k(float* __restrict__ X)
{
    __shared__ float red[256];
    int r = blockIdx.x, t = threadIdx.x;
    float ss = 0.f;
    for (int c = t; c < DD; c += 256) { float v = X[(size_t)r * DD + c]; ss += v * v; }
    red[t] = ss; __syncthreads();
    for (int s = 128; s > 0; s >>= 1) { if (t < s) red[t] += red[t + s]; __syncthreads(); }
    float sc = 1.0f / fmaxf(sqrtf(red[0]), 1e-12f);
    for (int c = t; c < DD; c += 256) X[(size_t)r * DD + c] *= sc;
}
__global__ void __launch_bounds__(256) silu_k(const float* __restrict__ h, float* __restrict__ a)
{
    size_t i = (size_t)blockIdx.x * 256 + threadIdx.x;
    float x = h[i];
    a[i] = x / (1.0f + expf(-x));
}
__global__ void __launch_bounds__(256) make_dy_k(const float* __restrict__ v, float* __restrict__ y)
{
    size_t i = (size_t)blockIdx.x * 256 + threadIdx.x;
    y[i] = (y[i] - v[i]) * (2.0f / (float)SD);
}
__global__ void __launch_bounds__(256) make_dh_k(const float* __restrict__ h, float* __restrict__ dh)
{
    size_t i = (size_t)blockIdx.x * 256 + threadIdx.x;
    float x = h[i];
    float sg = 1.0f / (1.0f + expf(-x));
    dh[i] *= sg * (1.0f + x * (1.0f - sg));
}
__global__ void __launch_bounds__(256) colsum_k(const float* __restrict__ M, float* __restrict__ out)
{
    int c = blockIdx.x * 256 + threadIdx.x;
    float s0 = 0.f, s1 = 0.f, s2 = 0.f, s3 = 0.f;
    for (int r = 0; r < SS; r += 4) {
        s0 += M[(size_t)(r+0)*DD + c]; s1 += M[(size_t)(r+1)*DD + c];
        s2 += M[(size_t)(r+2)*DD + c]; s3 += M[(size_t)(r+3)*DD + c];
    }
    out[c] = (s0 + s1) + (s2 + s3);
}
__global__ void __launch_bounds__(256) alpha_partial_k(const float* __restrict__ x,
                                                       const float* __restrict__ aw,
                                                       float* __restrict__ part)
{
    __shared__ float red[256];
    int b = blockIdx.x, t = threadIdx.x;
    size_t base = (size_t)b * 8192;
    float s = 0.f;
    for (int i = t; i < 8192; i += 256) s += x[base + i] * aw[i & (DD - 1)];
    red[t] = s; __syncthreads();
    for (int k = 128; k > 0; k >>= 1) { if (t < k) red[t] += red[t + k]; __syncthreads(); }
    if (t == 0) part[b] = red[0];
}
__global__ void __launch_bounds__(256) alpha_final_k(const float* __restrict__ ab,
                                                     const float* __restrict__ part,
                                                     float* __restrict__ alpha)
{
    __shared__ float red[256];
    int t = threadIdx.x;
    float s = 0.f;
    for (int i = t; i < 2048; i += 256) s += part[i];
    red[t] = s; __syncthreads();
    for (int k = 128; k > 0; k >>= 1) { if (t < k) red[t] += red[t + k]; __syncthreads(); }
    if (t == 0) alpha[0] = 1.0f / (1.0f + expf(-(red[0] / (float)SS + ab[0])));
}
__global__ void __launch_bounds__(256) fastw_k(const float* __restrict__ W,
                                               const float* __restrict__ Gm,
                                               float* __restrict__ Wf,
                                               const float* __restrict__ alpha)
{
    size_t i = (size_t)blockIdx.x * 256 + threadIdx.x;
    Wf[i] = (1.0f - alpha[0]) * W[i] - INNER_LR * Gm[i];
}
__global__ void __launch_bounds__(256) fastb_k(
    const float* __restrict__ b1, const float* __restrict__ gb1, float* __restrict__ b1f,
    const float* __restrict__ b2, const float* __restrict__ gb2, float* __restrict__ b2f,
    const float* __restrict__ alpha)
{
    int i = blockIdx.x * 256 + threadIdx.x;
    float am1 = 1.0f - alpha[0];
    b1f[i] = am1 * b1[i] - INNER_LR * gb1[i];
    b2f[i] = am1 * b2[i] - INNER_LR * gb2[i];
}

// ---------------- launch ----------------
extern "C" void kernel_launch(void* const* d_in, const int* in_sizes, int n_in,
                              void* d_out, int out_size)
{
    const float* x   = (const float*)d_in[0];
    const float* W_Q = (const float*)d_in[1];
    const float* W_K = (const float*)d_in[2];
    const float* W_V = (const float*)d_in[3];
    const float* aw  = (const float*)d_in[4];
    const float* ab  = (const float*)d_in[5];
    const float* W1  = (const float*)d_in[6];
    const float* b1  = (const float*)d_in[7];
    const float* W2  = (const float*)d_in[8];
    const float* b2  = (const float*)d_in[9];
    float* out = (float*)d_out;

    float* F; __nv_bfloat16* Bp;
    cudaGetSymbolAddress((void**)&F, g_f32);
    cudaGetSymbolAddress((void**)&Bp, g_bf);

    dim3 blk(256);
    dim3 gSD(DD / 128, SS / 128);
    dim3 gDD(DD / 128, DD / 128);
    int ew = SD / 256, ew4 = SD / 1024, ewW4 = DD2 / 1024;
    dim3 tSD(DD / 32, SS / 32), tDD(DD / 32, DD / 32);

    auto gemm_split = [&](const __nv_bfloat16* Ah, const __nv_bfloat16* Al,
                          const __nv_bfloat16* Bh, const __nv_bfloat16* Bl,
                          float* C, const float* bias, dim3 g, int Nw, int Kk) {
        gemm_mma<0><<<g, blk>>>(Ah, Bh, C, bias, Nw, Kk);
        gemm_mma<1><<<g, blk>>>(Ah, Bl, C, nullptr, Nw, Kk);
        gemm_mma<1><<<g, blk>>>(Al, Bh, C, nullptr, Nw, Kk);
    };

    // input conversions
    cvt_split_k<<<ew4, blk>>>((const float4*)x, (__nv_bfloat162*)(Bp+B_XH), (__nv_bfloat162*)(Bp+B_XL));
    cvt_split_k<<<ewW4, blk>>>((const float4*)W_Q, (__nv_bfloat162*)(Bp+B_WQH), (__nv_bfloat162*)(Bp+B_WQL));
    cvt_k<<<ewW4, blk>>>((const float4*)W_K, (__nv_bfloat162*)(Bp+B_WK));
    cvt_k<<<ewW4, blk>>>((const float4*)W_V, (__nv_bfloat162*)(Bp+B_WV));
    cvt_k<<<ewW4, blk>>>((const float4*)W1, (__nv_bfloat162*)(Bp+B_W1));
    cvt_k<<<ewW4, blk>>>((const float4*)W2, (__nv_bfloat162*)(Bp+B_W2));
    cvtT_k<<<tDD, blk>>>(W2, Bp + B_W2T, DD, DD);

    // alpha (exact fp32)
    alpha_partial_k<<<2048, blk>>>(x, aw, F + F_PART);
    alpha_final_k<<<1, blk>>>(ab, F + F_PART, F + F_ALPHA);

    // q (split), k, v
    gemm_split(Bp+B_XH, Bp+B_XL, Bp+B_WQH, Bp+B_WQL, F+F_Q, nullptr, gSD, DD, DD);
    gemm_mma<0><<<gSD, blk>>>(Bp+B_XH, Bp+B_WK, F+F_K, nullptr, DD, DD);
    gemm_mma<0><<<gSD, blk>>>(Bp+B_XH, Bp+B_WV, F+F_V, nullptr, DD, DD);
    rownorm_k<<<SS, blk>>>(F + F_Q);
    rownorm_k<<<SS, blk>>>(F + F_K);
    cvt_split_k<<<ew4, blk>>>((const float4*)(F+F_Q), (__nv_bfloat162*)(Bp+B_QH), (__nv_bfloat162*)(Bp+B_QL));
    cvt_k<<<ew4, blk>>>((const float4*)(F+F_K), (__nv_bfloat162*)(Bp+B_K));
    cvtT_k<<<tSD, blk>>>(F + F_K, Bp + B_KT, SS, DD);

    // forward MLP on k
    gemm_mma<0><<<gSD, blk>>>(Bp+B_K, Bp+B_W1, F+F_H, b1, DD, DD);
    silu_k<<<ew, blk>>>(F + F_H, F + F_A);
    cvt_k<<<ew4, blk>>>((const float4*)(F+F_A), (__nv_bfloat162*)(Bp+B_A));
    cvtT_k<<<tSD, blk>>>(F + F_A, Bp + B_AT, SS, DD);
    gemm_mma<0><<<gSD, blk>>>(Bp+B_A, Bp+B_W2, F+F_DY, b2, DD, DD);
    make_dy_k<<<ew, blk>>>(F + F_V, F + F_DY);
    cvt_k<<<ew4, blk>>>((const float4*)(F+F_DY), (__nv_bfloat162*)(Bp+B_DY));
    cvtT_k<<<tSD, blk>>>(F + F_DY, Bp + B_DYT, SS, DD);

    // gW2 = dy^T @ a ; gb2
    gemm_mma<0><<<gDD, blk>>>(Bp+B_DYT, Bp+B_AT, F+F_GW2, nullptr, DD, SS);
    colsum_k<<<DD / 256, blk>>>(F + F_DY, F + F_GB2);

    // dh = (dy @ W2) * dsilu(h) ; gW1 = dh^T @ k ; gb1
    gemm_mma<0><<<gSD, blk>>>(Bp+B_DY, Bp+B_W2T, F+F_DH, nullptr, DD, DD);
    make_dh_k<<<ew, blk>>>(F + F_H, F + F_DH);
    cvtT_k<<<tSD, blk>>>(F + F_DH, Bp + B_DHT, SS, DD);
    gemm_mma<0><<<gDD, blk>>>(Bp+B_DHT, Bp+B_KT, F+F_GW1, nullptr, DD, SS);
    colsum_k<<<DD / 256, blk>>>(F + F_DH, F + F_GB1);

    // fast weights
    fastw_k<<<DD2 / 256, blk>>>(W1, F + F_GW1, F + F_W1F, F + F_ALPHA);
    fastw_k<<<DD2 / 256, blk>>>(W2, F + F_GW2, F + F_W2F, F + F_ALPHA);
    fastb_k<<<DD / 256, blk>>>(b1, F+F_GB1, F+F_B1F, b2, F+F_GB2, F+F_B2F, F+F_ALPHA);
    cvt_split_k<<<ewW4, blk>>>((const float4*)(F+F_W1F), (__nv_bfloat162*)(Bp+B_W1FH), (__nv_bfloat162*)(Bp+B_W1FL));
    cvt_split_k<<<ewW4, blk>>>((const float4*)(F+F_W2F), (__nv_bfloat162*)(Bp+B_W2FH), (__nv_bfloat162*)(Bp+B_W2FL));

    // retrieve (split precision)
    gemm_split(Bp+B_QH, Bp+B_QL, Bp+B_W1FH, Bp+B_W1FL, F+F_H, F+F_B1F, gSD, DD, DD);
    silu_k<<<ew, blk>>>(F + F_H, F + F_A);
    cvt_split_k<<<ew4, blk>>>((const float4*)(F+F_A), (__nv_bfloat162*)(Bp+B_ARH), (__nv_bfloat162*)(Bp+B_ARL));
    gemm_split(Bp+B_ARH, Bp+B_ARL, Bp+B_W2FH, Bp+B_W2FL, out, F+F_B2F, gSD, DD, DD);
}

// round 10
// speedup vs baseline: 5.2297x; 1.2824x over previous
#include <cuda_runtime.h>
#include <cuda_bf16.h>
#include <math.h>
#include <stdint.h>

#define DD 2048
#define SS 8192
#define SD (SS*DD)
#define DD2 (DD*DD)
#define INNER_LR 0.01f

// ---------------- scratch arenas ----------------
#define F_Q   ((size_t)0*SD)
#define F_K   ((size_t)1*SD)
#define F_V   ((size_t)2*SD)
#define F_H   ((size_t)3*SD)
#define F_A   ((size_t)4*SD)
#define F_DY  ((size_t)5*SD)
#define F_DH  ((size_t)6*SD)
#define F_GW1 ((size_t)7*SD)
#define F_GW2 (F_GW1 + DD2)
#define F_W1F (F_GW2 + DD2)
#define F_W2F (F_W1F + DD2)
#define F_B1F (F_W2F + DD2)
#define F_B2F (F_B1F + DD)
#define F_GB1 (F_B2F + DD)
#define F_GB2 (F_GB1 + DD)
#define F_PART (F_GB2 + DD)
#define F_ALPHA (F_PART + 2048)
#define F_TOTAL (F_ALPHA + 64)
__device__ float g_f32[F_TOTAL];

#define B_XH   ((size_t)0*SD)
#define B_XL   ((size_t)1*SD)
#define B_QH   ((size_t)2*SD)
#define B_QL   ((size_t)3*SD)
#define B_K    ((size_t)4*SD)
#define B_KT   ((size_t)5*SD)
#define B_A    ((size_t)6*SD)
#define B_AT   ((size_t)7*SD)
#define B_DY   ((size_t)8*SD)
#define B_DYT  ((size_t)9*SD)
#define B_DHT  ((size_t)10*SD)
#define B_ARH  ((size_t)11*SD)
#define B_ARL  ((size_t)12*SD)
#define B_W    ((size_t)13*SD)
#define B_WQH  (B_W + (size_t)0*DD2)
#define B_WQL  (B_W + (size_t)1*DD2)
#define B_WK   (B_W + (size_t)2*DD2)
#define B_WV   (B_W + (size_t)3*DD2)
#define B_W1   (B_W + (size_t)4*DD2)
#define B_W2   (B_W + (size_t)5*DD2)
#define B_W2T  (B_W + (size_t)6*DD2)
#define B_W1FH (B_W + (size_t)7*DD2)
#define B_W1FL (B_W + (size_t)8*DD2)
#define B_W2FH (B_W + (size_t)9*DD2)
#define B_W2FL (B_W + (size_t)10*DD2)
#define B_TOTAL (B_W + (size_t)11*DD2)
__device__ __nv_bfloat16 g_bf[B_TOTAL];

// ---------------- PTX helpers ----------------
__device__ __forceinline__ uint32_t smem_u32(const void* p) {
    uint32_t a;
    asm("{ .reg .u64 t; cvta.to.shared.u64 t, %1; cvt.u32.u64 %0, t; }" : "=r"(a) : "l"(p));
    return a;
}
__device__ __forceinline__ void cp16(uint32_t s, const void* g) {
    asm volatile("cp.async.cg.shared.global [%0], [%1], 16;" :: "r"(s), "l"(g) : "memory");
}
__device__ __forceinline__ void cp_commit() {
    asm volatile("cp.async.commit_group;" ::: "memory");
}
__device__ __forceinline__ void ldm4(uint32_t* r, uint32_t a) {
    asm volatile("ldmatrix.sync.aligned.m8n8.x4.shared.b16 {%0,%1,%2,%3}, [%4];"
                 : "=r"(r[0]), "=r"(r[1]), "=r"(r[2]), "=r"(r[3]) : "r"(a));
}
__device__ __forceinline__ void mma16816(float* d, const uint32_t* a, uint32_t b0, uint32_t b1) {
    asm volatile("mma.sync.aligned.m16n8k16.row.col.f32.bf16.bf16.f32 "
        "{%0,%1,%2,%3}, {%4,%5,%6,%7}, {%8,%9}, {%0,%1,%2,%3};"
        : "+f"(d[0]), "+f"(d[1]), "+f"(d[2]), "+f"(d[3])
        : "r"(a[0]), "r"(a[1]), "r"(a[2]), "r"(a[3]), "r"(b0), "r"(b1));
}
// swizzled smem byte offset for [row][16B-chunk c]; 64B rows, 4 chunks
__device__ __forceinline__ uint32_t swz(int row, int c) {
    return (uint32_t)(row * 64 + ((c ^ (row & 3)) << 4));
}

// ---------------- mma.sync GEMM: C[M,N] = A@B^T (+ AhBl + AlBh if SPLIT) (+bias) ----
// Block 128x128, BK=32, NS-stage cp.async pipeline, 8 warps (4x2), warp tile 32x64.
template <int SPLIT, int NS>
__global__ void __launch_bounds__(256) gemm_mma(
    const __nv_bfloat16* __restrict__ A, const __nv_bfloat16* __restrict__ Alo,
    const __nv_bfloat16* __restrict__ B, const __nv_bfloat16* __restrict__ Blo,
    float* __restrict__ C, const float* __restrict__ bias, int Nw, int K)
{
    extern __shared__ __align__(128) char dynsm[];
    constexpr uint32_t STG = SPLIT ? 32768u : 16384u;
    const int tid = threadIdx.x;
    const int lane = tid & 31, wid = tid >> 5;
    const int wr = wid >> 1, wc = wid & 1;
    const int m0 = blockIdx.y * 128, n0 = blockIdx.x * 128;
    const uint32_t smA = smem_u32(dynsm);

    // cp.async assignments: 2 chunks per operand tile per thread
    uint32_t so[2]; size_t goA[2], goB[2];
#pragma unroll
    for (int i = 0; i < 2; i++) {
        int ch = tid * 2 + i, row = ch >> 2, c = ch & 3;
        so[i] = swz(row, c);
        goA[i] = (size_t)(m0 + row) * K + c * 8;
        goB[i] = (size_t)(n0 + row) * K + c * 8;
    }
    auto issue = [&](int ck) {
        uint32_t sb = smA + (uint32_t)(ck % NS) * STG;
        int k0 = ck << 5;
#pragma unroll
        for (int i = 0; i < 2; i++) cp16(sb + so[i], A + goA[i] + k0);
#pragma unroll
        for (int i = 0; i < 2; i++) cp16(sb + 8192u + so[i], B + goB[i] + k0);
        if constexpr (SPLIT != 0) {
#pragma unroll
            for (int i = 0; i < 2; i++) cp16(sb + 16384u + so[i], Alo + goA[i] + k0);
#pragma unroll
            for (int i = 0; i < 2; i++) cp16(sb + 24576u + so[i], Blo + goB[i] + k0);
        }
        cp_commit();
    };

    const int laA = lane & 15, lcA = lane >> 4;
    const int laB = (lane & 7) + ((lane >> 4) << 3);
    const int lcB = (lane >> 3) & 1;

    float acc[2][8][4];
#pragma unroll
    for (int mt = 0; mt < 2; mt++)
#pragma unroll
        for (int nt = 0; nt < 8; nt++)
#pragma unroll
            for (int j = 0; j < 4; j++) acc[mt][nt][j] = 0.f;

    const int nk = K >> 5;
#pragma unroll
    for (int p = 0; p < NS - 1; p++) issue(p);

    for (int ck = 0; ck < nk; ck++) {
        if (ck < nk - (NS - 2)) {
            if constexpr (NS == 4) asm volatile("cp.async.wait_group 2;" ::: "memory");
            else                   asm volatile("cp.async.wait_group 1;" ::: "memory");
        } else {
            asm volatile("cp.async.wait_group 0;" ::: "memory");
        }
        __syncthreads();

        uint32_t sb = smA + (uint32_t)(ck % NS) * STG;
#pragma unroll
        for (int ks = 0; ks < 2; ks++) {
            uint32_t af[2][4], bf[4][4];
#pragma unroll
            for (int mt = 0; mt < 2; mt++)
                ldm4(af[mt], sb + swz(wr * 32 + mt * 16 + laA, ks * 2 + lcA));
#pragma unroll
            for (int bt = 0; bt < 4; bt++)
                ldm4(bf[bt], sb + 8192u + swz(wc * 64 + bt * 16 + laB, ks * 2 + lcB));
#pragma unroll
            for (int mt = 0; mt < 2; mt++)
#pragma unroll
                for (int nt = 0; nt < 8; nt++) {
                    const uint32_t* bp = bf[nt >> 1];
                    if (nt & 1) mma16816(acc[mt][nt], af[mt], bp[2], bp[3]);
                    else        mma16816(acc[mt][nt], af[mt], bp[0], bp[1]);
                }
            if constexpr (SPLIT != 0) {
                uint32_t afl[2][4], bfl[4][4];
#pragma unroll
                for (int mt = 0; mt < 2; mt++)
                    ldm4(afl[mt], sb + 16384u + swz(wr * 32 + mt * 16 + laA, ks * 2 + lcA));
#pragma unroll
                for (int bt = 0; bt < 4; bt++)
                    ldm4(bfl[bt], sb + 24576u + swz(wc * 64 + bt * 16 + laB, ks * 2 + lcB));
#pragma unroll
                for (int mt = 0; mt < 2; mt++)
#pragma unroll
                    for (int nt = 0; nt < 8; nt++) {
                        const uint32_t* bp = bfl[nt >> 1];
                        if (nt & 1) mma16816(acc[mt][nt], af[mt], bp[2], bp[3]);
                        else        mma16816(acc[mt][nt], af[mt], bp[0], bp[1]);
                    }
#pragma unroll
                for (int mt = 0; mt < 2; mt++)
#pragma unroll
                    for (int nt = 0; nt < 8; nt++) {
                        const uint32_t* bp = bf[nt >> 1];
                        if (nt & 1) mma16816(acc[mt][nt], afl[mt], bp[2], bp[3]);
                        else        mma16816(acc[mt][nt], afl[mt], bp[0], bp[1]);
                    }
            }
        }
        if (ck + NS - 1 < nk) issue(ck + NS - 1);
    }

    // epilogue
#pragma unroll
    for (int mt = 0; mt < 2; mt++) {
        int r = m0 + wr * 32 + mt * 16 + (lane >> 2);
#pragma unroll
        for (int nt = 0; nt < 8; nt++) {
            int col = n0 + wc * 64 + nt * 8 + (lane & 3) * 2;
            float bx = 0.f, by = 0.f;
            if (bias) { bx = bias[col]; by = bias[col + 1]; }
            *(float2*)(C + (size_t)r * Nw + col) =
                make_float2(acc[mt][nt][0] + bx, acc[mt][nt][1] + by);
            *(float2*)(C + (size_t)(r + 8) * Nw + col) =
                make_float2(acc[mt][nt][2] + bx, acc[mt][nt][3] + by);
        }
    }
}

// ---------------- conversions ----------------
__global__ void __launch_bounds__(256) cvt_k(const float4* __restrict__ in,
                                             __nv_bfloat162* __restrict__ out)
{
    size_t i = (size_t)blockIdx.x * 256 + threadIdx.x;
    float4 v = in[i];
    out[2*i]   = __floats2bfloat162_rn(v.x, v.y);
    out[2*i+1] = __floats2bfloat162_rn(v.z, v.w);
}
__global__ void __launch_bounds__(256) cvt_split_k(const float4* __restrict__ in,
                                                   __nv_bfloat162* __restrict__ oh,
                                                   __nv_bfloat162* __restrict__ ol)
{
    size_t i = (size_t)blockIdx.x * 256 + threadIdx.x;
    float4 v = in[i];
    float f[4] = { v.x, v.y, v.z, v.w };
    __nv_bfloat16 h[4], l[4];
#pragma unroll
    for (int j = 0; j < 4; j++) {
        h[j] = __float2bfloat16(f[j]);
        l[j] = __float2bfloat16(f[j] - __bfloat162float(h[j]));
    }
    oh[2*i]   = __nv_bfloat162(h[0], h[1]);
    oh[2*i+1] = __nv_bfloat162(h[2], h[3]);
    ol[2*i]   = __nv_bfloat162(l[0], l[1]);
    ol[2*i+1] = __nv_bfloat162(l[2], l[3]);
}
__global__ void __launch_bounds__(256) cvtT_k(const float* __restrict__ in,
                                              __nv_bfloat16* __restrict__ out, int R, int Cc)
{
    __shared__ float tile[32][33];
    int cb = blockIdx.x * 32, rb = blockIdx.y * 32;
    int tx = threadIdx.x & 31, ty = threadIdx.x >> 5;
#pragma unroll
    for (int i = 0; i < 32; i += 8)
        tile[ty + i][tx] = in[(size_t)(rb + ty + i) * Cc + cb + tx];
    __syncthreads();
#pragma unroll
    for (int i = 0; i < 32; i += 8)
        out[(size_t)(cb + ty + i) * R + rb + tx] = __float2bfloat16(tile[tx][ty + i]);
}

// ---------------- fused row-l2norm variants ----------------
// q: normalize and emit split bf16 (no fp32 output needed)
__global__ void __launch_bounds__(256) rownorm_split_k(const float* __restrict__ X,
                                                       __nv_bfloat16* __restrict__ oh,
                                                       __nv_bfloat16* __restrict__ ol)
{
    __shared__ float red[256];
    int r = blockIdx.x, t = threadIdx.x;
    float ss = 0.f;
    for (int c = t; c < DD; c += 256) { float v = X[(size_t)r * DD + c]; ss += v * v; }
    red[t] = ss; __syncthreads();
    for (int s = 128; s > 0; s >>= 1) { if (t < s) red[t] += red[t + s]; __syncthreads(); }
    float sc = 1.0f / fmaxf(sqrtf(red[0]), 1e-12f);
    for (int c = t; c < DD; c += 256) {
        float v = X[(size_t)r * DD + c] * sc;
        __nv_bfloat16 h = __float2bfloat16(v);
        oh[(size_t)r * DD + c] = h;
        ol[(size_t)r * DD + c] = __float2bfloat16(v - __bfloat162float(h));
    }
}
// k: normalize in place (fp32 kept for cvtT) + emit plain bf16
__global__ void __launch_bounds__(256) rownorm_bf_k(float* __restrict__ X,
                                                    __nv_bfloat16* __restrict__ ob)
{
    __shared__ float red[256];
    int r = blockIdx.x, t = threadIdx.x;
    float ss = 0.f;
    for (int c = t; c < DD; c += 256) { float v = X[(size_t)r * DD + c]; ss += v * v; }
    red[t] = ss; __syncthreads();
    for (int s = 128; s > 0; s >>= 1) { if (t < s) red[t] += red[t + s]; __syncthreads(); }
    float sc = 1.0f / fmaxf(sqrtf(red[0]), 1e-12f);
    for (int c = t; c < DD; c += 256) {
        float v = X[(size_t)r * DD + c] * sc;
        X[(size_t)r * DD + c] = v;
        ob[(size_t)r * DD + c] = __float2bfloat16(v);
    }
}

// ---------------- fused elementwise ----------------
__global__ void __launch_bounds__(256) silu_bf_k(const float4* __restrict__ h,
                                                 float4* __restrict__ a,
                                                 __nv_bfloat162* __restrict__ ab)
{
    size_t i = (size_t)blockIdx.x * 256 + threadIdx.x;
    float4 x = h[i], o;
    o.x = x.x / (1.0f + expf(-x.x)); o.y = x.y / (1.0f + expf(-x.y));
    o.z = x.z / (1.0f + expf(-x.z)); o.w = x.w / (1.0f + expf(-x.w));
    a[i] = o;
    ab[2*i]   = __floats2bfloat162_rn(o.x, o.y);
    ab[2*i+1] = __floats2bfloat162_rn(o.z, o.w);
}
__global__ void __launch_bounds__(256) silu_split_k(const float4* __restrict__ h,
                                                    __nv_bfloat162* __restrict__ oh,
                                                    __nv_bfloat162* __restrict__ ol)
{
    size_t i = (size_t)blockIdx.x * 256 + threadIdx.x;
    float4 x = h[i];
    float f[4] = { x.x / (1.0f + expf(-x.x)), x.y / (1.0f + expf(-x.y)),
                   x.z / (1.0f + expf(-x.z)), x.w / (1.0f + expf(-x.w)) };
    __nv_bfloat16 hh[4], ll[4];
#pragma unroll
    for (int j = 0; j < 4; j++) {
        hh[j] = __float2bfloat16(f[j]);
        ll[j] = __float2bfloat16(f[j] - __bfloat162float(hh[j]));
    }
    oh[2*i]   = __nv_bfloat162(hh[0], hh[1]);
    oh[2*i+1] = __nv_bfloat162(hh[2], hh[3]);
    ol[2*i]   = __nv_bfloat162(ll[0], ll[1]);
    ol[2*i+1] = __nv_bfloat162(ll[2], ll[3]);
}
__global__ void __launch_bounds__(256) make_dy_bf_k(const float4* __restrict__ v,
                                                    float4* __restrict__ y,
                                                    __nv_bfloat162* __restrict__ ob)
{
    size_t i = (size_t)blockIdx.x * 256 + threadIdx.x;
    const float sc = 2.0f / (float)SD;
    float4 yy = y[i], vv = v[i], o;
    o.x = (yy.x - vv.x) * sc; o.y = (yy.y - vv.y) * sc;
    o.z = (yy.z - vv.z) * sc; o.w = (yy.w - vv.w) * sc;
    y[i] = o;
    ob[2*i]   = __floats2bfloat162_rn(o.x, o.y);
    ob[2*i+1] = __floats2bfloat162_rn(o.z, o.w);
}
__global__ void __launch_bounds__(256) make_dh_k(const float4* __restrict__ h,
                                                 float4* __restrict__ dh)
{
    size_t i = (size_t)blockIdx.x * 256 + threadIdx.x;
    float4 x = h[i], d = dh[i];
    float f[4] = { x.x, x.y, x.z, x.w };
    float g[4] = { d.x, d.y, d.z, d.w };
#pragma unroll
    for (int j = 0; j < 4; j++) {
        float sg = 1.0f / (1.0f + expf(-f[j]));
        g[j] *= sg * (1.0f + f[j] * (1.0f - sg));
    }
    dh[i] = make_float4(g[0], g[1], g[2], g[3]);
}
__global__ void __launch_bounds__(256) colsum_k(const float* __restrict__ M, float* __restrict__ out)
{
    int c = blockIdx.x * 256 + threadIdx.x;
    float s0 = 0.f, s1 = 0.f, s2 = 0.f, s3 = 0.f;
    for (int r = 0; r < SS; r += 4) {
        s0 += M[(size_t)(r+0)*DD + c]; s1 += M[(size_t)(r+1)*DD + c];
        s2 += M[(size_t)(r+2)*DD + c]; s3 += M[(size_t)(r+3)*DD + c];
    }
    out[c] = (s0 + s1) + (s2 + s3);
}
__global__ void __launch_bounds__(256) alpha_partial_k(const float* __restrict__ x,
                                                       const float* __restrict__ aw,
                                                       float* __restrict__ part)
{
    __shared__ float red[256];
    int b = blockIdx.x, t = threadIdx.x;
    size_t base = (size_t)b * 8192;
    float s = 0.f;
    for (int i = t; i < 8192; i += 256) s += x[base + i] * aw[i & (DD - 1)];
    red[t] = s; __syncthreads();
    for (int k = 128; k > 0; k >>= 1) { if (t < k) red[t] += red[t + k]; __syncthreads(); }
    if (t == 0) part[b] = red[0];
}
__global__ void __launch_bounds__(256) alpha_final_k(const float* __restrict__ ab,
                                                     const float* __restrict__ part,
                                                     float* __restrict__ alpha)
{
    __shared__ float red[256];
    int t = threadIdx.x;
    float s = 0.f;
    for (int i = t; i < 2048; i += 256) s += part[i];
    red[t] = s; __syncthreads();
    for (int k = 128; k > 0; k >>= 1) { if (t < k) red[t] += red[t + k]; __syncthreads(); }
    if (t == 0) alpha[0] = 1.0f / (1.0f + expf(-(red[0] / (float)SS + ab[0])));
}
// fast weight + split bf16 conversion fused
__global__ void __launch_bounds__(256) fastw_split_k(const float4* __restrict__ W,
                                                     const float4* __restrict__ Gm,
                                                     float4* __restrict__ Wf,
                                                     __nv_bfloat162* __restrict__ oh,
                                                     __nv_bfloat162* __restrict__ ol,
                                                     const float* __restrict__ alpha)
{
    size_t i = (size_t)blockIdx.x * 256 + threadIdx.x;
    float am1 = 1.0f - alpha[0];
    float4 w = W[i], g = Gm[i], o;
    o.x = am1 * w.x - INNER_LR * g.x; o.y = am1 * w.y - INNER_LR * g.y;
    o.z = am1 * w.z - INNER_LR * g.z; o.w = am1 * w.w - INNER_LR * g.w;
    Wf[i] = o;
    float f[4] = { o.x, o.y, o.z, o.w };
    __nv_bfloat16 hh[4], ll[4];
#pragma unroll
    for (int j = 0; j < 4; j++) {
        hh[j] = __float2bfloat16(f[j]);
        ll[j] = __float2bfloat16(f[j] - __bfloat162float(hh[j]));
    }
    oh[2*i]   = __nv_bfloat162(hh[0], hh[1]);
    oh[2*i+1] = __nv_bfloat162(hh[2], hh[3]);
    ol[2*i]   = __nv_bfloat162(ll[0], ll[1]);
    ol[2*i+1] = __nv_bfloat162(ll[2], ll[3]);
}
__global__ void __launch_bounds__(256) fastb_k(
    const float* __restrict__ b1, const float* __restrict__ gb1, float* __restrict__ b1f,
    const float* __restrict__ b2, const float* __restrict__ gb2, float* __restrict__ b2f,
    const float* __restrict__ alpha)
{
    int i = blockIdx.x * 256 + threadIdx.x;
    float am1 = 1.0f - alpha[0];
    b1f[i] = am1 * b1[i] - INNER_LR * gb1[i];
    b2f[i] = am1 * b2[i] - INNER_LR * gb2[i];
}

// ---------------- launch ----------------
extern "C" void kernel_launch(void* const* d_in, const int* in_sizes, int n_in,
                              void* d_out, int out_size)
{
    const float* x   = (const float*)d_in[0];
    const float* W_Q = (const float*)d_in[1];
    const float* W_K = (const float*)d_in[2];
    const float* W_V = (const float*)d_in[3];
    const float* aw  = (const float*)d_in[4];
    const float* ab  = (const float*)d_in[5];
    const float* W1  = (const float*)d_in[6];
    const float* b1  = (const float*)d_in[7];
    const float* W2  = (const float*)d_in[8];
    const float* b2  = (const float*)d_in[9];
    float* out = (float*)d_out;

    float* F; __nv_bfloat16* Bp;
    cudaGetSymbolAddress((void**)&F, g_f32);
    cudaGetSymbolAddress((void**)&Bp, g_bf);

    const int SM0 = 4 * 16384;   // plain: NS=4
    const int SM1 = 3 * 32768;   // split: NS=3
    cudaFuncSetAttribute((const void*)gemm_mma<0,4>, cudaFuncAttributeMaxDynamicSharedMemorySize, SM0);
    cudaFuncSetAttribute((const void*)gemm_mma<1,3>, cudaFuncAttributeMaxDynamicSharedMemorySize, SM1);

    dim3 blk(256);
    dim3 gSD(DD / 128, SS / 128);
    dim3 gDD(DD / 128, DD / 128);
    int ew4 = SD / 1024, ewW4 = DD2 / 1024;
    dim3 tSD(DD / 32, SS / 32), tDD(DD / 32, DD / 32);

    // input conversions
    cvt_split_k<<<ew4, blk>>>((const float4*)x, (__nv_bfloat162*)(Bp+B_XH), (__nv_bfloat162*)(Bp+B_XL));
    cvt_split_k<<<ewW4, blk>>>((const float4*)W_Q, (__nv_bfloat162*)(Bp+B_WQH), (__nv_bfloat162*)(Bp+B_WQL));
    cvt_k<<<ewW4, blk>>>((const float4*)W_K, (__nv_bfloat162*)(Bp+B_WK));
    cvt_k<<<ewW4, blk>>>((const float4*)W_V, (__nv_bfloat162*)(Bp+B_WV));
    cvt_k<<<ewW4, blk>>>((const float4*)W1, (__nv_bfloat162*)(Bp+B_W1));
    cvt_k<<<ewW4, blk>>>((const float4*)W2, (__nv_bfloat162*)(Bp+B_W2));
    cvtT_k<<<tDD, blk>>>(W2, Bp + B_W2T, DD, DD);

    // alpha (exact fp32)
    alpha_partial_k<<<2048, blk>>>(x, aw, F + F_PART);
    alpha_final_k<<<1, blk>>>(ab, F + F_PART, F + F_ALPHA);

    // q (split), k, v
    gemm_mma<1,3><<<gSD, blk, SM1>>>(Bp+B_XH, Bp+B_XL, Bp+B_WQH, Bp+B_WQL, F+F_Q, nullptr, DD, DD);
    gemm_mma<0,4><<<gSD, blk, SM0>>>(Bp+B_XH, nullptr, Bp+B_WK, nullptr, F+F_K, nullptr, DD, DD);
    gemm_mma<0,4><<<gSD, blk, SM0>>>(Bp+B_XH, nullptr, Bp+B_WV, nullptr, F+F_V, nullptr, DD, DD);
    rownorm_split_k<<<SS, blk>>>(F + F_Q, Bp + B_QH, Bp + B_QL);
    rownorm_bf_k<<<SS, blk>>>(F + F_K, Bp + B_K);
    cvtT_k<<<tSD, blk>>>(F + F_K, Bp + B_KT, SS, DD);

    // forward MLP on k
    gemm_mma<0,4><<<gSD, blk, SM0>>>(Bp+B_K, nullptr, Bp+B_W1, nullptr, F+F_H, b1, DD, DD);
    silu_bf_k<<<ew4, blk>>>((const float4*)(F+F_H), (float4*)(F+F_A), (__nv_bfloat162*)(Bp+B_A));
    cvtT_k<<<tSD, blk>>>(F + F_A, Bp + B_AT, SS, DD);
    gemm_mma<0,4><<<gSD, blk, SM0>>>(Bp+B_A, nullptr, Bp+B_W2, nullptr, F+F_DY, b2, DD, DD);
    make_dy_bf_k<<<ew4, blk>>>((const float4*)(F+F_V), (float4*)(F+F_DY), (__nv_bfloat162*)(Bp+B_DY));
    cvtT_k<<<tSD, blk>>>(F + F_DY, Bp + B_DYT, SS, DD);

    // gW2 = dy^T @ a ; gb2
    gemm_mma<0,4><<<gDD, blk, SM0>>>(Bp+B_DYT, nullptr, Bp+B_AT, nullptr, F+F_GW2, nullptr, DD, SS);
    colsum_k<<<DD / 256, blk>>>(F + F_DY, F + F_GB2);

    // dh = (dy @ W2) * dsilu(h) ; gW1 = dh^T @ k ; gb1
    gemm_mma<0,4><<<gSD, blk, SM0>>>(Bp+B_DY, nullptr, Bp+B_W2T, nullptr, F+F_DH, nullptr, DD, DD);
    make_dh_k<<<ew4, blk>>>((const float4*)(F+F_H), (float4*)(F+F_DH));
    cvtT_k<<<tSD, blk>>>(F + F_DH, Bp + B_DHT, SS, DD);
    gemm_mma<0,4><<<gDD, blk, SM0>>>(Bp+B_DHT, nullptr, Bp+B_KT, nullptr, F+F_GW1, nullptr, DD, SS);
    colsum_k<<<DD / 256, blk>>>(F + F_DH, F + F_GB1);

    // fast weights (+ fused split conversion)
    fastw_split_k<<<ewW4, blk>>>((const float4*)W1, (const float4*)(F+F_GW1), (float4*)(F+F_W1F),
                                 (__nv_bfloat162*)(Bp+B_W1FH), (__nv_bfloat162*)(Bp+B_W1FL), F+F_ALPHA);
    fastw_split_k<<<ewW4, blk>>>((const float4*)W2, (const float4*)(F+F_GW2), (float4*)(F+F_W2F),
                                 (__nv_bfloat162*)(Bp+B_W2FH), (__nv_bfloat162*)(Bp+B_W2FL), F+F_ALPHA);
    fastb_k<<<DD / 256, blk>>>(b1, F+F_GB1, F+F_B1F, b2, F+F_GB2, F+F_B2F, F+F_ALPHA);

    // retrieve (split precision)
    gemm_mma<1,3><<<gSD, blk, SM1>>>(Bp+B_QH, Bp+B_QL, Bp+B_W1FH, Bp+B_W1FL, F+F_H, F+F_B1F, DD, DD);
    silu_split_k<<<ew4, blk>>>((const float4*)(F+F_H), (__nv_bfloat162*)(Bp+B_ARH), (__nv_bfloat162*)(Bp+B_ARL));
    gemm_mma<1,3><<<gSD, blk, SM1>>>(Bp+B_ARH, Bp+B_ARL, Bp+B_W2FH, Bp+B_W2FL, out, F+F_B2F, DD, DD);
}

// round 14
// speedup vs baseline: 5.4497x; 1.0421x over previous
#include <cuda_runtime.h>
#include <cuda_bf16.h>
#include <math.h>
#include <stdint.h>

#define DD 2048
#define SS 8192
#define SD (SS*DD)
#define DD2 (DD*DD)
#define INNER_LR 0.01f

// ---------------- scratch arenas ----------------
#define F_Q   ((size_t)0*SD)
#define F_K   ((size_t)1*SD)
#define F_V   ((size_t)2*SD)
#define F_H   ((size_t)3*SD)
#define F_A   ((size_t)4*SD)
#define F_DY  ((size_t)5*SD)
#define F_DH  ((size_t)6*SD)
#define F_GW1 ((size_t)7*SD)
#define F_GW2 (F_GW1 + DD2)
#define F_W1F (F_GW2 + DD2)
#define F_W2F (F_W1F + DD2)
#define F_B1F (F_W2F + DD2)
#define F_B2F (F_B1F + DD)
#define F_GB1 (F_B2F + DD)
#define F_GB2 (F_GB1 + DD)
#define F_PART (F_GB2 + DD)
#define F_ALPHA (F_PART + 2048)
#define F_TOTAL (F_ALPHA + 64)
__device__ float g_f32[F_TOTAL];

#define B_XH   ((size_t)0*SD)
#define B_XL   ((size_t)1*SD)
#define B_QH   ((size_t)2*SD)
#define B_QL   ((size_t)3*SD)
#define B_K    ((size_t)4*SD)
#define B_KT   ((size_t)5*SD)
#define B_A    ((size_t)6*SD)
#define B_AT   ((size_t)7*SD)
#define B_DY   ((size_t)8*SD)
#define B_DYT  ((size_t)9*SD)
#define B_DHT  ((size_t)10*SD)
#define B_ARH  ((size_t)11*SD)
#define B_ARL  ((size_t)12*SD)
#define B_W    ((size_t)13*SD)
#define B_WQH  (B_W + (size_t)0*DD2)
#define B_WQL  (B_W + (size_t)1*DD2)
#define B_WK   (B_W + (size_t)2*DD2)
#define B_WV   (B_W + (size_t)3*DD2)
#define B_W1   (B_W + (size_t)4*DD2)
#define B_W2   (B_W + (size_t)5*DD2)
#define B_W2T  (B_W + (size_t)6*DD2)
#define B_W1FH (B_W + (size_t)7*DD2)
#define B_W1FL (B_W + (size_t)8*DD2)
#define B_W2FH (B_W + (size_t)9*DD2)
#define B_W2FL (B_W + (size_t)10*DD2)
#define B_TOTAL (B_W + (size_t)11*DD2)
__device__ __nv_bfloat16 g_bf[B_TOTAL];

// ---------------- PTX helpers ----------------
__device__ __forceinline__ uint32_t smem_u32(const void* p) {
    uint32_t a;
    asm("{ .reg .u64 t; cvta.to.shared.u64 t, %1; cvt.u32.u64 %0, t; }" : "=r"(a) : "l"(p));
    return a;
}
__device__ __forceinline__ void cp16(uint32_t s, const void* g) {
    asm volatile("cp.async.cg.shared.global [%0], [%1], 16;" :: "r"(s), "l"(g) : "memory");
}
__device__ __forceinline__ void cp_commit() {
    asm volatile("cp.async.commit_group;" ::: "memory");
}
__device__ __forceinline__ void ldm4(uint32_t* r, uint32_t a) {
    asm volatile("ldmatrix.sync.aligned.m8n8.x4.shared.b16 {%0,%1,%2,%3}, [%4];"
                 : "=r"(r[0]), "=r"(r[1]), "=r"(r[2]), "=r"(r[3]) : "r"(a));
}
__device__ __forceinline__ void mma16816(float* d, const uint32_t* a, uint32_t b0, uint32_t b1) {
    asm volatile("mma.sync.aligned.m16n8k16.row.col.f32.bf16.bf16.f32 "
        "{%0,%1,%2,%3}, {%4,%5,%6,%7}, {%8,%9}, {%0,%1,%2,%3};"
        : "+f"(d[0]), "+f"(d[1]), "+f"(d[2]), "+f"(d[3])
        : "r"(a[0]), "r"(a[1]), "r"(a[2]), "r"(a[3]), "r"(b0), "r"(b1));
}
__device__ __forceinline__ uint32_t swz(int row, int c) {
    return (uint32_t)(row * 64 + ((c ^ (row & 3)) << 4));
}

// ---------------- plain GEMM, block 256x128, warp tile 64x64, NS=4 ----------------
__global__ void __launch_bounds__(256) gemm_big(
    const __nv_bfloat16* __restrict__ A, const __nv_bfloat16* __restrict__ B,
    float* __restrict__ C, const float* __restrict__ bias, int Nw, int K)
{
    extern __shared__ __align__(128) char dynsm[];
    constexpr int NS = 4;
    constexpr uint32_t STG = 24576u;     // A 16KB + B 8KB
    const int tid = threadIdx.x;
    const int lane = tid & 31, wid = tid >> 5;
    const int wr = wid >> 1, wc = wid & 1;
    const int m0 = blockIdx.y * 256, n0 = blockIdx.x * 128;
    const uint32_t smA = smem_u32(dynsm);

    // cp.async: A 4 chunks, B 2 chunks per thread
    uint32_t soA[4], soB[2]; size_t goA[4], goB[2];
#pragma unroll
    for (int i = 0; i < 4; i++) {
        int ch = i * 256 + tid, row = ch >> 2, c = ch & 3;
        soA[i] = swz(row, c);
        goA[i] = (size_t)(m0 + row) * K + c * 8;
    }
#pragma unroll
    for (int i = 0; i < 2; i++) {
        int ch = i * 256 + tid, row = ch >> 2, c = ch & 3;
        soB[i] = swz(row, c);
        goB[i] = (size_t)(n0 + row) * K + c * 8;
    }
    auto issue = [&](int ck) {
        uint32_t sb = smA + (uint32_t)(ck % NS) * STG;
        int k0 = ck << 5;
#pragma unroll
        for (int i = 0; i < 4; i++) cp16(sb + soA[i], A + goA[i] + k0);
#pragma unroll
        for (int i = 0; i < 2; i++) cp16(sb + 16384u + soB[i], B + goB[i] + k0);
        cp_commit();
    };

    const int laA = lane & 15, lcA = lane >> 4;
    const int laB = (lane & 7) + ((lane >> 4) << 3);
    const int lcB = (lane >> 3) & 1;

    float acc[4][8][4];
#pragma unroll
    for (int mt = 0; mt < 4; mt++)
#pragma unroll
        for (int nt = 0; nt < 8; nt++)
#pragma unroll
            for (int j = 0; j < 4; j++) acc[mt][nt][j] = 0.f;

    const int nk = K >> 5;
#pragma unroll
    for (int p = 0; p < NS - 1; p++) issue(p);

    for (int ck = 0; ck < nk; ck++) {
        if (ck < nk - 2) asm volatile("cp.async.wait_group 2;" ::: "memory");
        else             asm volatile("cp.async.wait_group 0;" ::: "memory");
        __syncthreads();

        uint32_t sb = smA + (uint32_t)(ck % NS) * STG;
#pragma unroll
        for (int ks = 0; ks < 2; ks++) {
            uint32_t af[4][4], bf[4][4];
#pragma unroll
            for (int mt = 0; mt < 4; mt++)
                ldm4(af[mt], sb + swz(wr * 64 + mt * 16 + laA, ks * 2 + lcA));
#pragma unroll
            for (int bt = 0; bt < 4; bt++)
                ldm4(bf[bt], sb + 16384u + swz(wc * 64 + bt * 16 + laB, ks * 2 + lcB));
#pragma unroll
            for (int mt = 0; mt < 4; mt++)
#pragma unroll
                for (int nt = 0; nt < 8; nt++) {
                    const uint32_t* bp = bf[nt >> 1];
                    if (nt & 1) mma16816(acc[mt][nt], af[mt], bp[2], bp[3]);
                    else        mma16816(acc[mt][nt], af[mt], bp[0], bp[1]);
                }
        }
        if (ck + NS - 1 < nk) issue(ck + NS - 1);
    }

#pragma unroll
    for (int mt = 0; mt < 4; mt++) {
        int r = m0 + wr * 64 + mt * 16 + (lane >> 2);
#pragma unroll
        for (int nt = 0; nt < 8; nt++) {
            int col = n0 + wc * 64 + nt * 8 + (lane & 3) * 2;
            float bx = 0.f, by = 0.f;
            if (bias) { bx = bias[col]; by = bias[col + 1]; }
            *(float2*)(C + (size_t)r * Nw + col) =
                make_float2(acc[mt][nt][0] + bx, acc[mt][nt][1] + by);
            *(float2*)(C + (size_t)(r + 8) * Nw + col) =
                make_float2(acc[mt][nt][2] + bx, acc[mt][nt][3] + by);
        }
    }
}

// ---------------- fused split GEMM: C = AhBh^T + AhBl^T + AlBh^T (+bias) ----------------
// Block 128x128, BK=32, NS=3, warp tile 32x64.
__global__ void __launch_bounds__(256) gemm_split(
    const __nv_bfloat16* __restrict__ A, const __nv_bfloat16* __restrict__ Alo,
    const __nv_bfloat16* __restrict__ B, const __nv_bfloat16* __restrict__ Blo,
    float* __restrict__ C, const float* __restrict__ bias, int Nw, int K)
{
    extern __shared__ __align__(128) char dynsm[];
    constexpr int NS = 3;
    constexpr uint32_t STG = 32768u;
    const int tid = threadIdx.x;
    const int lane = tid & 31, wid = tid >> 5;
    const int wr = wid >> 1, wc = wid & 1;
    const int m0 = blockIdx.y * 128, n0 = blockIdx.x * 128;
    const uint32_t smA = smem_u32(dynsm);

    uint32_t so[2]; size_t goA[2], goB[2];
#pragma unroll
    for (int i = 0; i < 2; i++) {
        int ch = tid * 2 + i, row = ch >> 2, c = ch & 3;
        so[i] = swz(row, c);
        goA[i] = (size_t)(m0 + row) * K + c * 8;
        goB[i] = (size_t)(n0 + row) * K + c * 8;
    }
    auto issue = [&](int ck) {
        uint32_t sb = smA + (uint32_t)(ck % NS) * STG;
        int k0 = ck << 5;
#pragma unroll
        for (int i = 0; i < 2; i++) cp16(sb + so[i], A + goA[i] + k0);
#pragma unroll
        for (int i = 0; i < 2; i++) cp16(sb + 8192u + so[i], B + goB[i] + k0);
#pragma unroll
        for (int i = 0; i < 2; i++) cp16(sb + 16384u + so[i], Alo + goA[i] + k0);
#pragma unroll
        for (int i = 0; i < 2; i++) cp16(sb + 24576u + so[i], Blo + goB[i] + k0);
        cp_commit();
    };

    const int laA = lane & 15, lcA = lane >> 4;
    const int laB = (lane & 7) + ((lane >> 4) << 3);
    const int lcB = (lane >> 3) & 1;

    float acc[2][8][4];
#pragma unroll
    for (int mt = 0; mt < 2; mt++)
#pragma unroll
        for (int nt = 0; nt < 8; nt++)
#pragma unroll
            for (int j = 0; j < 4; j++) acc[mt][nt][j] = 0.f;

    const int nk = K >> 5;
#pragma unroll
    for (int p = 0; p < NS - 1; p++) issue(p);

    for (int ck = 0; ck < nk; ck++) {
        if (ck < nk - 1) asm volatile("cp.async.wait_group 1;" ::: "memory");
        else             asm volatile("cp.async.wait_group 0;" ::: "memory");
        __syncthreads();

        uint32_t sb = smA + (uint32_t)(ck % NS) * STG;
#pragma unroll
        for (int ks = 0; ks < 2; ks++) {
            uint32_t af[2][4], bf[4][4];
#pragma unroll
            for (int mt = 0; mt < 2; mt++)
                ldm4(af[mt], sb + swz(wr * 32 + mt * 16 + laA, ks * 2 + lcA));
#pragma unroll
            for (int bt = 0; bt < 4; bt++)
                ldm4(bf[bt], sb + 8192u + swz(wc * 64 + bt * 16 + laB, ks * 2 + lcB));
#pragma unroll
            for (int mt = 0; mt < 2; mt++)
#pragma unroll
                for (int nt = 0; nt < 8; nt++) {
                    const uint32_t* bp = bf[nt >> 1];
                    if (nt & 1) mma16816(acc[mt][nt], af[mt], bp[2], bp[3]);
                    else        mma16816(acc[mt][nt], af[mt], bp[0], bp[1]);
                }
            uint32_t afl[2][4], bfl[4][4];
#pragma unroll
            for (int mt = 0; mt < 2; mt++)
                ldm4(afl[mt], sb + 16384u + swz(wr * 32 + mt * 16 + laA, ks * 2 + lcA));
#pragma unroll
            for (int bt = 0; bt < 4; bt++)
                ldm4(bfl[bt], sb + 24576u + swz(wc * 64 + bt * 16 + laB, ks * 2 + lcB));
#pragma unroll
            for (int mt = 0; mt < 2; mt++)
#pragma unroll
                for (int nt = 0; nt < 8; nt++) {
                    const uint32_t* bp = bfl[nt >> 1];
                    if (nt & 1) mma16816(acc[mt][nt], af[mt], bp[2], bp[3]);
                    else        mma16816(acc[mt][nt], af[mt], bp[0], bp[1]);
                }
#pragma unroll
            for (int mt = 0; mt < 2; mt++)
#pragma unroll
                for (int nt = 0; nt < 8; nt++) {
                    const uint32_t* bp = bf[nt >> 1];
                    if (nt & 1) mma16816(acc[mt][nt], afl[mt], bp[2], bp[3]);
                    else        mma16816(acc[mt][nt], afl[mt], bp[0], bp[1]);
                }
        }
        if (ck + NS - 1 < nk) issue(ck + NS - 1);
    }

#pragma unroll
    for (int mt = 0; mt < 2; mt++) {
        int r = m0 + wr * 32 + mt * 16 + (lane >> 2);
#pragma unroll
        for (int nt = 0; nt < 8; nt++) {
            int col = n0 + wc * 64 + nt * 8 + (lane & 3) * 2;
            float bx = 0.f, by = 0.f;
            if (bias) { bx = bias[col]; by = bias[col + 1]; }
            *(float2*)(C + (size_t)r * Nw + col) =
                make_float2(acc[mt][nt][0] + bx, acc[mt][nt][1] + by);
            *(float2*)(C + (size_t)(r + 8) * Nw + col) =
                make_float2(acc[mt][nt][2] + bx, acc[mt][nt][3] + by);
        }
    }
}

// ---------------- conversions ----------------
__global__ void __launch_bounds__(256) cvt_k(const float4* __restrict__ in,
                                             __nv_bfloat162* __restrict__ out)
{
    size_t i = (size_t)blockIdx.x * 256 + threadIdx.x;
    float4 v = in[i];
    out[2*i]   = __floats2bfloat162_rn(v.x, v.y);
    out[2*i+1] = __floats2bfloat162_rn(v.z, v.w);
}
__global__ void __launch_bounds__(256) cvt_split_k(const float4* __restrict__ in,
                                                   __nv_bfloat162* __restrict__ oh,
                                                   __nv_bfloat162* __restrict__ ol)
{
    size_t i = (size_t)blockIdx.x * 256 + threadIdx.x;
    float4 v = in[i];
    float f[4] = { v.x, v.y, v.z, v.w };
    __nv_bfloat16 h[4], l[4];
#pragma unroll
    for (int j = 0; j < 4; j++) {
        h[j] = __float2bfloat16(f[j]);
        l[j] = __float2bfloat16(f[j] - __bfloat162float(h[j]));
    }
    oh[2*i]   = __nv_bfloat162(h[0], h[1]);
    oh[2*i+1] = __nv_bfloat162(h[2], h[3]);
    ol[2*i]   = __nv_bfloat162(l[0], l[1]);
    ol[2*i+1] = __nv_bfloat162(l[2], l[3]);
}
__global__ void __launch_bounds__(256) cvtT_k(const float* __restrict__ in,
                                              __nv_bfloat16* __restrict__ out, int R, int Cc)
{
    __shared__ float tile[32][33];
    int cb = blockIdx.x * 32, rb = blockIdx.y * 32;
    int tx = threadIdx.x & 31, ty = threadIdx.x >> 5;
#pragma unroll
    for (int i = 0; i < 32; i += 8)
        tile[ty + i][tx] = in[(size_t)(rb + ty + i) * Cc + cb + tx];
    __syncthreads();
#pragma unroll
    for (int i = 0; i < 32; i += 8)
        out[(size_t)(cb + ty + i) * R + rb + tx] = __float2bfloat16(tile[tx][ty + i]);
}

// ---------------- fused row-l2norm ----------------
__global__ void __launch_bounds__(256) rownorm_split_k(const float* __restrict__ X,
                                                       __nv_bfloat16* __restrict__ oh,
                                                       __nv_bfloat16* __restrict__ ol)
{
    __shared__ float red[256];
    int r = blockIdx.x, t = threadIdx.x;
    float ss = 0.f;
    for (int c = t; c < DD; c += 256) { float v = X[(size_t)r * DD + c]; ss += v * v; }
    red[t] = ss; __syncthreads();
    for (int s = 128; s > 0; s >>= 1) { if (t < s) red[t] += red[t + s]; __syncthreads(); }
    float sc = 1.0f / fmaxf(sqrtf(red[0]), 1e-12f);
    for (int c = t; c < DD; c += 256) {
        float v = X[(size_t)r * DD + c] * sc;
        __nv_bfloat16 h = __float2bfloat16(v);
        oh[(size_t)r * DD + c] = h;
        ol[(size_t)r * DD + c] = __float2bfloat16(v - __bfloat162float(h));
    }
}
__global__ void __launch_bounds__(256) rownorm_bf_k(float* __restrict__ X,
                                                    __nv_bfloat16* __restrict__ ob)
{
    __shared__ float red[256];
    int r = blockIdx.x, t = threadIdx.x;
    float ss = 0.f;
    for (int c = t; c < DD; c += 256) { float v = X[(size_t)r * DD + c]; ss += v * v; }
    red[t] = ss; __syncthreads();
    for (int s = 128; s > 0; s >>= 1) { if (t < s) red[t] += red[t + s]; __syncthreads(); }
    float sc = 1.0f / fmaxf(sqrtf(red[0]), 1e-12f);
    for (int c = t; c < DD; c += 256) {
        float v = X[(size_t)r * DD + c] * sc;
        X[(size_t)r * DD + c] = v;
        ob[(size_t)r * DD + c] = __float2bfloat16(v);
    }
}

// ---------------- fused elementwise ----------------
__global__ void __launch_bounds__(256) silu_bf_k(const float4* __restrict__ h,
                                                 float4* __restrict__ a,
                                                 __nv_bfloat162* __restrict__ ab)
{
    size_t i = (size_t)blockIdx.x * 256 + threadIdx.x;
    float4 x = h[i], o;
    o.x = x.x / (1.0f + expf(-x.x)); o.y = x.y / (1.0f + expf(-x.y));
    o.z = x.z / (1.0f + expf(-x.z)); o.w = x.w / (1.0f + expf(-x.w));
    a[i] = o;
    ab[2*i]   = __floats2bfloat162_rn(o.x, o.y);
    ab[2*i+1] = __floats2bfloat162_rn(o.z, o.w);
}
__global__ void __launch_bounds__(256) silu_split_k(const float4* __restrict__ h,
                                                    __nv_bfloat162* __restrict__ oh,
                                                    __nv_bfloat162* __restrict__ ol)
{
    size_t i = (size_t)blockIdx.x * 256 + threadIdx.x;
    float4 x = h[i];
    float f[4] = { x.x / (1.0f + expf(-x.x)), x.y / (1.0f + expf(-x.y)),
                   x.z / (1.0f + expf(-x.z)), x.w / (1.0f + expf(-x.w)) };
    __nv_bfloat16 hh[4], ll[4];
#pragma unroll
    for (int j = 0; j < 4; j++) {
        hh[j] = __float2bfloat16(f[j]);
        ll[j] = __float2bfloat16(f[j] - __bfloat162float(hh[j]));
    }
    oh[2*i]   = __nv_bfloat162(hh[0], hh[1]);
    oh[2*i+1] = __nv_bfloat162(hh[2], hh[3]);
    ol[2*i]   = __nv_bfloat162(ll[0], ll[1]);
    ol[2*i+1] = __nv_bfloat162(ll[2], ll[3]);
}
__global__ void __launch_bounds__(256) make_dy_bf_k(const float4* __restrict__ v,
                                                    float4* __restrict__ y,
                                                    __nv_bfloat162* __restrict__ ob)
{
    size_t i = (size_t)blockIdx.x * 256 + threadIdx.x;
    const float sc = 2.0f / (float)SD;
    float4 yy = y[i], vv = v[i], o;
    o.x = (yy.x - vv.x) * sc; o.y = (yy.y - vv.y) * sc;
    o.z = (yy.z - vv.z) * sc; o.w = (yy.w - vv.w) * sc;
    y[i] = o;
    ob[2*i]   = __floats2bfloat162_rn(o.x, o.y);
    ob[2*i+1] = __floats2bfloat162_rn(o.z, o.w);
}
__global__ void __launch_bounds__(256) make_dh_k(const float4* __restrict__ h,
                                                 float4* __restrict__ dh)
{
    size_t i = (size_t)blockIdx.x * 256 + threadIdx.x;
    float4 x = h[i], d = dh[i];
    float f[4] = { x.x, x.y, x.z, x.w };
    float g[4] = { d.x, d.y, d.z, d.w };
#pragma unroll
    for (int j = 0; j < 4; j++) {
        float sg = 1.0f / (1.0f + expf(-f[j]));
        g[j] *= sg * (1.0f + f[j] * (1.0f - sg));
    }
    dh[i] = make_float4(g[0], g[1], g[2], g[3]);
}
__global__ void __launch_bounds__(256) colsum_k(const float* __restrict__ M, float* __restrict__ out)
{
    int c = blockIdx.x * 256 + threadIdx.x;
    float s0 = 0.f, s1 = 0.f, s2 = 0.f, s3 = 0.f;
    for (int r = 0; r < SS; r += 4) {
        s0 += M[(size_t)(r+0)*DD + c]; s1 += M[(size_t)(r+1)*DD + c];
        s2 += M[(size_t)(r+2)*DD + c]; s3 += M[(size_t)(r+3)*DD + c];
    }
    out[c] = (s0 + s1) + (s2 + s3);
}
__global__ void __launch_bounds__(256) alpha_partial_k(const float* __restrict__ x,
                                                       const float* __restrict__ aw,
                                                       float* __restrict__ part)
{
    __shared__ float red[256];
    int b = blockIdx.x, t = threadIdx.x;
    size_t base = (size_t)b * 8192;
    float s = 0.f;
    for (int i = t; i < 8192; i += 256) s += x[base + i] * aw[i & (DD - 1)];
    red[t] = s; __syncthreads();
    for (int k = 128; k > 0; k >>= 1) { if (t < k) red[t] += red[t + k]; __syncthreads(); }
    if (t == 0) part[b] = red[0];
}
__global__ void __launch_bounds__(256) alpha_final_k(const float* __restrict__ ab,
                                                     const float* __restrict__ part,
                                                     float* __restrict__ alpha)
{
    __shared__ float red[256];
    int t = threadIdx.x;
    float s = 0.f;
    for (int i = t; i < 2048; i += 256) s += part[i];
    red[t] = s; __syncthreads();
    for (int k = 128; k > 0; k >>= 1) { if (t < k) red[t] += red[t + k]; __syncthreads(); }
    if (t == 0) alpha[0] = 1.0f / (1.0f + expf(-(red[0] / (float)SS + ab[0])));
}
__global__ void __launch_bounds__(256) fastw_split_k(const float4* __restrict__ W,
                                                     const float4* __restrict__ Gm,
                                                     float4* __restrict__ Wf,
                                                     __nv_bfloat162* __restrict__ oh,
                                                     __nv_bfloat162* __restrict__ ol,
                                                     const float* __restrict__ alpha)
{
    size_t i = (size_t)blockIdx.x * 256 + threadIdx.x;
    float am1 = 1.0f - alpha[0];
    float4 w = W[i], g = Gm[i], o;
    o.x = am1 * w.x - INNER_LR * g.x; o.y = am1 * w.y - INNER_LR * g.y;
    o.z = am1 * w.z - INNER_LR * g.z; o.w = am1 * w.w - INNER_LR * g.w;
    Wf[i] = o;
    float f[4] = { o.x, o.y, o.z, o.w };
    __nv_bfloat16 hh[4], ll[4];
#pragma unroll
    for (int j = 0; j < 4; j++) {
        hh[j] = __float2bfloat16(f[j]);
        ll[j] = __float2bfloat16(f[j] - __bfloat162float(hh[j]));
    }
    oh[2*i]   = __nv_bfloat162(hh[0], hh[1]);
    oh[2*i+1] = __nv_bfloat162(hh[2], hh[3]);
    ol[2*i]   = __nv_bfloat162(ll[0], ll[1]);
    ol[2*i+1] = __nv_bfloat162(ll[2], ll[3]);
}
__global__ void __launch_bounds__(256) fastb_k(
    const float* __restrict__ b1, const float* __restrict__ gb1, float* __restrict__ b1f,
    const float* __restrict__ b2, const float* __restrict__ gb2, float* __restrict__ b2f,
    const float* __restrict__ alpha)
{
    int i = blockIdx.x * 256 + threadIdx.x;
    float am1 = 1.0f - alpha[0];
    b1f[i] = am1 * b1[i] - INNER_LR * gb1[i];
    b2f[i] = am1 * b2[i] - INNER_LR * gb2[i];
}

// ---------------- launch ----------------
extern "C" void kernel_launch(void* const* d_in, const int* in_sizes, int n_in,
                              void* d_out, int out_size)
{
    const float* x   = (const float*)d_in[0];
    const float* W_Q = (const float*)d_in[1];
    const float* W_K = (const float*)d_in[2];
    const float* W_V = (const float*)d_in[3];
    const float* aw  = (const float*)d_in[4];
    const float* ab  = (const float*)d_in[5];
    const float* W1  = (const float*)d_in[6];
    const float* b1  = (const float*)d_in[7];
    const float* W2  = (const float*)d_in[8];
    const float* b2  = (const float*)d_in[9];
    float* out = (float*)d_out;

    float* F; __nv_bfloat16* Bp;
    cudaGetSymbolAddress((void**)&F, g_f32);
    cudaGetSymbolAddress((void**)&Bp, g_bf);

    const int SMB = 4 * 24576;   // gemm_big: NS=4, 96KB
    const int SMS = 3 * 32768;   // gemm_split: NS=3, 96KB
    cudaFuncSetAttribute((const void*)gemm_big, cudaFuncAttributeMaxDynamicSharedMemorySize, SMB);
    cudaFuncSetAttribute((const void*)gemm_split, cudaFuncAttributeMaxDynamicSharedMemorySize, SMS);

    dim3 blk(256);
    dim3 gSDb(DD / 128, SS / 256);   // big: [S,D] outputs
    dim3 gDDb(DD / 128, DD / 256);   // big: [D,D] outputs
    dim3 gSDs(DD / 128, SS / 128);   // split
    int ew4 = SD / 1024, ewW4 = DD2 / 1024;
    dim3 tSD(DD / 32, SS / 32), tDD(DD / 32, DD / 32);

    // input conversions
    cvt_split_k<<<ew4, blk>>>((const float4*)x, (__nv_bfloat162*)(Bp+B_XH), (__nv_bfloat162*)(Bp+B_XL));
    cvt_split_k<<<ewW4, blk>>>((const float4*)W_Q, (__nv_bfloat162*)(Bp+B_WQH), (__nv_bfloat162*)(Bp+B_WQL));
    cvt_k<<<ewW4, blk>>>((const float4*)W_K, (__nv_bfloat162*)(Bp+B_WK));
    cvt_k<<<ewW4, blk>>>((const float4*)W_V, (__nv_bfloat162*)(Bp+B_WV));
    cvt_k<<<ewW4, blk>>>((const float4*)W1, (__nv_bfloat162*)(Bp+B_W1));
    cvt_k<<<ewW4, blk>>>((const float4*)W2, (__nv_bfloat162*)(Bp+B_W2));
    cvtT_k<<<tDD, blk>>>(W2, Bp + B_W2T, DD, DD);

    // alpha (exact fp32)
    alpha_partial_k<<<2048, blk>>>(x, aw, F + F_PART);
    alpha_final_k<<<1, blk>>>(ab, F + F_PART, F + F_ALPHA);

    // q (split), k, v
    gemm_split<<<gSDs, blk, SMS>>>(Bp+B_XH, Bp+B_XL, Bp+B_WQH, Bp+B_WQL, F+F_Q, nullptr, DD, DD);
    gemm_big<<<gSDb, blk, SMB>>>(Bp+B_XH, Bp+B_WK, F+F_K, nullptr, DD, DD);
    gemm_big<<<gSDb, blk, SMB>>>(Bp+B_XH, Bp+B_WV, F+F_V, nullptr, DD, DD);
    rownorm_split_k<<<SS, blk>>>(F + F_Q, Bp + B_QH, Bp + B_QL);
    rownorm_bf_k<<<SS, blk>>>(F + F_K, Bp + B_K);
    cvtT_k<<<tSD, blk>>>(F + F_K, Bp + B_KT, SS, DD);

    // forward MLP on k
    gemm_big<<<gSDb, blk, SMB>>>(Bp+B_K, Bp+B_W1, F+F_H, b1, DD, DD);
    silu_bf_k<<<ew4, blk>>>((const float4*)(F+F_H), (float4*)(F+F_A), (__nv_bfloat162*)(Bp+B_A));
    cvtT_k<<<tSD, blk>>>(F + F_A, Bp + B_AT, SS, DD);
    gemm_big<<<gSDb, blk, SMB>>>(Bp+B_A, Bp+B_W2, F+F_DY, b2, DD, DD);
    make_dy_bf_k<<<ew4, blk>>>((const float4*)(F+F_V), (float4*)(F+F_DY), (__nv_bfloat162*)(Bp+B_DY));
    cvtT_k<<<tSD, blk>>>(F + F_DY, Bp + B_DYT, SS, DD);

    // gW2 = dy^T @ a ; gb2
    gemm_big<<<gDDb, blk, SMB>>>(Bp+B_DYT, Bp+B_AT, F+F_GW2, nullptr, DD, SS);
    colsum_k<<<DD / 256, blk>>>(F + F_DY, F + F_GB2);

    // dh = (dy @ W2) * dsilu(h) ; gW1 = dh^T @ k ; gb1
    gemm_big<<<gSDb, blk, SMB>>>(Bp+B_DY, Bp+B_W2T, F+F_DH, nullptr, DD, DD);
    make_dh_k<<<ew4, blk>>>((const float4*)(F+F_H), (float4*)(F+F_DH));
    cvtT_k<<<tSD, blk>>>(F + F_DH, Bp + B_DHT, SS, DD);
    gemm_big<<<gDDb, blk, SMB>>>(Bp+B_DHT, Bp+B_KT, F+F_GW1, nullptr, DD, SS);
    colsum_k<<<DD / 256, blk>>>(F + F_DH, F + F_GB1);

    // fast weights (+ fused split conversion)
    fastw_split_k<<<ewW4, blk>>>((const float4*)W1, (const float4*)(F+F_GW1), (float4*)(F+F_W1F),
                                 (__nv_bfloat162*)(Bp+B_W1FH), (__nv_bfloat162*)(Bp+B_W1FL), F+F_ALPHA);
    fastw_split_k<<<ewW4, blk>>>((const float4*)W2, (const float4*)(F+F_GW2), (float4*)(F+F_W2F),
                                 (__nv_bfloat162*)(Bp+B_W2FH), (__nv_bfloat162*)(Bp+B_W2FL), F+F_ALPHA);
    fastb_k<<<DD / 256, blk>>>(b1, F+F_GB1, F+F_B1F, b2, F+F_GB2, F+F_B2F, F+F_ALPHA);

    // retrieve (split precision)
    gemm_split<<<gSDs, blk, SMS>>>(Bp+B_QH, Bp+B_QL, Bp+B_W1FH, Bp+B_W1FL, F+F_H, F+F_B1F, DD, DD);
    silu_split_k<<<ew4, blk>>>((const float4*)(F+F_H), (__nv_bfloat162*)(Bp+B_ARH), (__nv_bfloat162*)(Bp+B_ARL));
    gemm_split<<<gSDs, blk, SMS>>>(Bp+B_ARH, Bp+B_ARL, Bp+B_W2FH, Bp+B_W2FL, out, F+F_B2F, DD, DD);
}